// round 1
// baseline (speedup 1.0000x reference)
#include <cuda_runtime.h>
#include <cstdint>

// Shifted-window multi-view attention, fused flash kernel.
// Shapes (hardcoded from the problem): B=8, M=3, H=W=96, C=128, NS=4
//   -> windows: 128 (= b*16 + sh*4 + sw), L = 24*24 = 576, KV len = L*M = 1728
// q   : [8, 9216, 128]  fp32
// k,v : [8, 3, 9216, 128] fp32
// out : [8, 9216, 128]  fp32
//
// Index semantics (derived from the reference):
//  * roll(-12,-12): window element (sh,i,sw,j) reads global pos
//       gr=(sh*24+i+12)%96, gc=(sw*24+j+12)%96
//  * KV flatten: kv = 3*l + mm  (view index mm fastest)
//  * mask quirk: jnp.tile(mask,(b,1,m)) -> mask column = kv % 576 (NOT l)
//  * mask value: 0 if region(q)==region(kcol) else -100, regions from the
//    UNROLLED image grid: boundaries at 72 and 84.
//  * scores scaled by 1/sqrt(128) BEFORE mask add.
//  * output scatter is the same (sh,i,sw,j)->global map as the q gather.

#define NT 256

__device__ __forceinline__ int swz(int row, int col) {
    // 128-float pitch, XOR bits 2..4 of col with row bits 2..4:
    // keeps float4 alignment, spreads 16 distinct rows over 8 float4 bins.
    return (row << 7) + (col ^ (((row >> 2) & 7) << 2));
}

__device__ __forceinline__ int reg1(int x) {
    // region boundaries: h - wsh = 72, h - ssh = 84
    return (x < 72) ? 0 : ((x < 84) ? 1 : 2);
}

extern "C" __global__ void __launch_bounds__(NT, 2)
mv_attn_kernel(const float* __restrict__ qg,
               const float* __restrict__ kg,
               const float* __restrict__ vg,
               float* __restrict__ outg)
{
    extern __shared__ float smem[];
    float* Qs = smem;              // 64 x 128 (swizzled)
    float* Ks = smem + 64 * 128;   // 64 x 128 (swizzled; reused as P after S)
    float* Vs = smem + 2 * 64 * 128;
    int*   regK = (int*)(smem + 3 * 64 * 128);   // 64 ints

    const int tid = threadIdx.x;
    const int ty  = tid >> 4;     // 0..15 -> q rows 4*ty..4*ty+3
    const int tx  = tid & 15;     // 0..15 -> S cols 4*tx..+3, O cols 8*tx..+7
    const int win = blockIdx.y;   // 0..127
    const int b   = win >> 4;
    const int sh  = (win >> 2) & 3;
    const int sw  = win & 3;
    const int q0  = blockIdx.x << 6;   // 64 queries per CTA, 9 CTAs cover 576

    const float scale = 0.08838834764831845f;  // 1/sqrt(128)

    // ---- load Q block (scaled) ----
    #pragma unroll
    for (int it = 0; it < 8; ++it) {
        int idx = tid + it * NT;            // 0..2047
        int r   = idx >> 5;                 // 0..63
        int c4  = (idx & 31) << 2;          // 0..124
        int ql  = q0 + r;
        int i   = ql / 24, j = ql - 24 * i;
        int gr  = (sh * 24 + i + 12) % 96;
        int gc  = (sw * 24 + j + 12) % 96;
        const float4 f = *(const float4*)(qg + ((size_t)(b * 9216 + gr * 96 + gc) << 7) + c4);
        *(float4*)&Qs[swz(r, c4)] = make_float4(f.x * scale, f.y * scale, f.z * scale, f.w * scale);
    }

    // region ids for my 4 q rows
    int regQ[4];
    #pragma unroll
    for (int qi = 0; qi < 4; ++qi) {
        int ql = q0 + 4 * ty + qi;
        int i = ql / 24, j = ql - 24 * i;
        regQ[qi] = reg1(sh * 24 + i) * 3 + reg1(sw * 24 + j);
    }

    float m_i[4], l_i[4], o[4][8];
    #pragma unroll
    for (int qi = 0; qi < 4; ++qi) {
        m_i[qi] = -1e30f;
        l_i[qi] = 0.0f;
        #pragma unroll
        for (int ci = 0; ci < 8; ++ci) o[qi][ci] = 0.0f;
    }

    for (int kv0 = 0; kv0 < 1728; kv0 += 64) {
        __syncthreads();  // prior readers of Ks/Vs (and Qs producers on iter 0) done

        // ---- load K,V tile (64 kv rows x 128 ch) ----
        #pragma unroll
        for (int it = 0; it < 8; ++it) {
            int idx = tid + it * NT;
            int r   = idx >> 5;
            int c4  = (idx & 31) << 2;
            int kv  = kv0 + r;
            int l   = kv / 3;
            int mm  = kv - 3 * l;
            int i   = l / 24, j = l - 24 * i;
            int gr  = (sh * 24 + i + 12) % 96;
            int gc  = (sw * 24 + j + 12) % 96;
            size_t base = (((size_t)(b * 3 + mm) * 9216 + gr * 96 + gc) << 7) + c4;
            *(float4*)&Ks[swz(r, c4)] = *(const float4*)(kg + base);
            *(float4*)&Vs[swz(r, c4)] = *(const float4*)(vg + base);
        }
        if (tid < 64) {
            int kcol = (kv0 + tid) % 576;         // faithful tile() quirk
            int i = kcol / 24, j = kcol - 24 * i;
            regK[tid] = reg1(sh * 24 + i) * 3 + reg1(sw * 24 + j);
        }
        __syncthreads();

        // ---- S = (Q*scale) @ K^T, 4q x 4t per thread ----
        float s[4][4];
        #pragma unroll
        for (int qi = 0; qi < 4; ++qi)
            #pragma unroll
            for (int ti = 0; ti < 4; ++ti) s[qi][ti] = 0.0f;

        #pragma unroll 2
        for (int c4 = 0; c4 < 128; c4 += 4) {
            float4 qf[4], kf[4];
            #pragma unroll
            for (int qi = 0; qi < 4; ++qi) qf[qi] = *(const float4*)&Qs[swz(4 * ty + qi, c4)];
            #pragma unroll
            for (int ti = 0; ti < 4; ++ti) kf[ti] = *(const float4*)&Ks[swz(4 * tx + ti, c4)];
            #pragma unroll
            for (int qi = 0; qi < 4; ++qi)
                #pragma unroll
                for (int ti = 0; ti < 4; ++ti) {
                    s[qi][ti] += qf[qi].x * kf[ti].x;
                    s[qi][ti] += qf[qi].y * kf[ti].y;
                    s[qi][ti] += qf[qi].z * kf[ti].z;
                    s[qi][ti] += qf[qi].w * kf[ti].w;
                }
        }

        // ---- mask ----
        int rkv[4];
        #pragma unroll
        for (int ti = 0; ti < 4; ++ti) rkv[ti] = regK[4 * tx + ti];
        #pragma unroll
        for (int qi = 0; qi < 4; ++qi)
            #pragma unroll
            for (int ti = 0; ti < 4; ++ti)
                if (regQ[qi] != rkv[ti]) s[qi][ti] -= 100.0f;

        // ---- online softmax (row groups span the 16 lanes with same ty) ----
        #pragma unroll
        for (int qi = 0; qi < 4; ++qi) {
            float mx = fmaxf(fmaxf(s[qi][0], s[qi][1]), fmaxf(s[qi][2], s[qi][3]));
            mx = fmaxf(mx, __shfl_xor_sync(0xffffffffu, mx, 1));
            mx = fmaxf(mx, __shfl_xor_sync(0xffffffffu, mx, 2));
            mx = fmaxf(mx, __shfl_xor_sync(0xffffffffu, mx, 4));
            mx = fmaxf(mx, __shfl_xor_sync(0xffffffffu, mx, 8));
            float mnew  = fmaxf(m_i[qi], mx);
            float alpha = __expf(m_i[qi] - mnew);
            m_i[qi] = mnew;
            float rs = 0.0f;
            #pragma unroll
            for (int ti = 0; ti < 4; ++ti) {
                float p = __expf(s[qi][ti] - mnew);
                s[qi][ti] = p;
                rs += p;
            }
            rs += __shfl_xor_sync(0xffffffffu, rs, 1);
            rs += __shfl_xor_sync(0xffffffffu, rs, 2);
            rs += __shfl_xor_sync(0xffffffffu, rs, 4);
            rs += __shfl_xor_sync(0xffffffffu, rs, 8);
            l_i[qi] = l_i[qi] * alpha + rs;
            #pragma unroll
            for (int ci = 0; ci < 8; ++ci) o[qi][ci] *= alpha;
        }

        __syncthreads();  // everyone done reading Ks (K data)

        // ---- store P into Ks buffer (64 x 64, swizzled) ----
        #pragma unroll
        for (int qi = 0; qi < 4; ++qi)
            *(float4*)&Ks[swz(4 * ty + qi, 4 * tx)] =
                make_float4(s[qi][0], s[qi][1], s[qi][2], s[qi][3]);
        __syncthreads();

        // ---- O += P @ V, 4q x 8c per thread ----
        #pragma unroll 4
        for (int t = 0; t < 64; ++t) {
            float4 v0 = *(const float4*)&Vs[swz(t, tx << 3)];
            float4 v1 = *(const float4*)&Vs[swz(t, (tx << 3) + 4)];
            #pragma unroll
            for (int qi = 0; qi < 4; ++qi) {
                float p = Ks[swz(4 * ty + qi, t)];
                o[qi][0] += p * v0.x; o[qi][1] += p * v0.y;
                o[qi][2] += p * v0.z; o[qi][3] += p * v0.w;
                o[qi][4] += p * v1.x; o[qi][5] += p * v1.y;
                o[qi][6] += p * v1.z; o[qi][7] += p * v1.w;
            }
        }
    }

    // ---- epilogue: normalize and scatter (inverse roll/merge == same map) ----
    #pragma unroll
    for (int qi = 0; qi < 4; ++qi) {
        float inv = 1.0f / l_i[qi];
        int ql = q0 + 4 * ty + qi;
        int i = ql / 24, j = ql - 24 * i;
        int gr = (sh * 24 + i + 12) % 96;
        int gc = (sw * 24 + j + 12) % 96;
        float* dst = outg + ((size_t)(b * 9216 + gr * 96 + gc) << 7) + (tx << 3);
        *(float4*)(dst)     = make_float4(o[qi][0] * inv, o[qi][1] * inv,
                                          o[qi][2] * inv, o[qi][3] * inv);
        *(float4*)(dst + 4) = make_float4(o[qi][4] * inv, o[qi][5] * inv,
                                          o[qi][6] * inv, o[qi][7] * inv);
    }
}

extern "C" void kernel_launch(void* const* d_in, const int* in_sizes, int n_in,
                              void* d_out, int out_size)
{
    const float* q = (const float*)d_in[0];
    const float* k = (const float*)d_in[1];
    const float* v = (const float*)d_in[2];
    float* out = (float*)d_out;

    const int smem_bytes = (3 * 64 * 128) * 4 + 64 * 4;  // 98560 B
    cudaFuncSetAttribute(mv_attn_kernel,
                         cudaFuncAttributeMaxDynamicSharedMemorySize, smem_bytes);

    dim3 grid(9, 128, 1);   // 9 q-blocks of 64 over L=576, 128 windows
    mv_attn_kernel<<<grid, NT, smem_bytes>>>(q, k, v, out);
}

// round 2
// speedup vs baseline: 1.6242x; 1.6242x over previous
#include <cuda_runtime.h>
#include <cstdint>

// Shifted-window multi-view attention, tf32 tensor-core flash kernel.
// B=8, M=3, H=W=96, C=128, NS=4 -> 128 windows, L=576, KV=1728.
// QK^T in 3xTF32 (hi/lo split, fp32-grade), PV in 1-pass tf32.
// CTA: 128 threads (4 warps), 64 q rows (16 per warp), KV tile = 48.

#define NT 128
#define KVT 48

// smem layout (floats):
//  Qs  [64][128]  fp32, scaled, swizzled  c^ (4*(row&7))       : 8192 f
//  Khl [48][128] x2 interleaved (hi,lo) tf32, swz c^(4*(kv&7)) : 12288 f  (P overlays)
//  Vs  [48][128]  tf32, swizzled c^(8*(kv&3))                  : 6144 f
//  regK[1728] char
#define QS_OFF   0
#define KHL_OFF  8192
#define VS_OFF   20480
#define SMEM_F   26624
#define REGK_B   (SMEM_F * 4)
#define SMEM_BYTES (REGK_B + 1792)

__device__ __forceinline__ uint32_t f2tf(float x) {
    uint32_t r; asm("cvt.rna.tf32.f32 %0, %1;" : "=r"(r) : "f"(x)); return r;
}
__device__ __forceinline__ void mma8(float c[4],
    uint32_t a0, uint32_t a1, uint32_t a2, uint32_t a3, uint32_t b0, uint32_t b1) {
    asm volatile("mma.sync.aligned.m16n8k8.row.col.f32.tf32.tf32.f32 "
        "{%0,%1,%2,%3},{%4,%5,%6,%7},{%8,%9},{%0,%1,%2,%3};"
        : "+f"(c[0]), "+f"(c[1]), "+f"(c[2]), "+f"(c[3])
        : "r"(a0), "r"(a1), "r"(a2), "r"(a3), "r"(b0), "r"(b1));
}
__device__ __forceinline__ int reg1(int x) { return (x < 72) ? 0 : ((x < 84) ? 1 : 2); }

extern "C" __global__ void __launch_bounds__(NT)
mv_attn_tc(const float* __restrict__ qg,
           const float* __restrict__ kg,
           const float* __restrict__ vg,
           float* __restrict__ outg)
{
    extern __shared__ float smem[];
    float* Qs  = smem + QS_OFF;
    float* Khl = smem + KHL_OFF;
    float* Vs  = smem + VS_OFF;
    char*  regK = (char*)smem + REGK_B;

    const int tid  = threadIdx.x;
    const int warp = tid >> 5;
    const int lane = tid & 31;
    const int gr   = lane >> 2;   // 0..7  (mma "groupID")
    const int tig  = lane & 3;    // 0..3
    const int woff = warp << 4;   // 16 q rows per warp

    const int win = blockIdx.y;
    const int b   = win >> 4;
    const int sh  = (win >> 2) & 3;
    const int sw  = win & 3;
    const int q0  = blockIdx.x << 6;

    const float scale = 0.08838834764831845f;  // 1/sqrt(128)

    // ---- load Q (scaled, swizzled fp32) ----
    #pragma unroll
    for (int it = 0; it < 16; ++it) {
        int idx = tid + it * NT;            // 0..2047
        int r   = idx >> 5;                 // 0..63
        int c4  = (idx & 31) << 2;
        int ql  = q0 + r;
        int i = ql / 24, j = ql - 24 * i;
        int grow = (sh * 24 + i + 12) % 96;
        int gcol = (sw * 24 + j + 12) % 96;
        float4 f = *(const float4*)(qg + ((size_t)(b * 9216 + grow * 96 + gcol) << 7) + c4);
        int cs = c4 ^ ((r & 7) << 2);
        *(float4*)&Qs[r * 128 + cs] =
            make_float4(f.x * scale, f.y * scale, f.z * scale, f.w * scale);
    }
    // ---- precompute region id for all 1728 kv columns (tile() quirk: kv%576) ----
    for (int idx = tid; idx < 1728; idx += NT) {
        int kcol = idx % 576;
        int i = kcol / 24, j = kcol - 24 * i;
        regK[idx] = (char)(reg1(sh * 24 + i) * 3 + reg1(sw * 24 + j));
    }

    // region ids for my 2 rows
    int rq0, rq1;
    {
        int ql = q0 + woff + gr;
        int i = ql / 24, j = ql - 24 * i;
        rq0 = reg1(sh * 24 + i) * 3 + reg1(sw * 24 + j);
        ql += 8; i = ql / 24; j = ql - 24 * i;
        rq1 = reg1(sh * 24 + i) * 3 + reg1(sw * 24 + j);
    }

    float O[16][4];
    #pragma unroll
    for (int nt = 0; nt < 16; ++nt)
        #pragma unroll
        for (int v = 0; v < 4; ++v) O[nt][v] = 0.0f;
    float m0 = -1e30f, m1 = -1e30f, l0 = 0.0f, l1 = 0.0f;

    float* Pw = Khl + warp * (16 * 68);   // per-warp P staging (overlay on Khl)

    for (int kv0 = 0; kv0 < 1728; kv0 += KVT) {
        __syncthreads();   // previous PV readers of Khl(P)/Vs done; Qs visible on iter 0

        // ---- load K tile -> (hi,lo) tf32 pairs, V tile -> tf32 ----
        #pragma unroll
        for (int it = 0; it < 12; ++it) {
            int idx = tid + it * NT;        // 0..1535
            int r   = idx >> 5;             // 0..47
            int c4  = (idx & 31) << 2;
            int kv  = kv0 + r;
            int l   = kv / 3;
            int mm  = kv - 3 * l;
            int i = l / 24, j = l - 24 * i;
            int grow = (sh * 24 + i + 12) % 96;
            int gcol = (sw * 24 + j + 12) % 96;
            size_t base = (((size_t)(b * 3 + mm) * 9216 + grow * 96 + gcol) << 7) + c4;

            float4 kf = *(const float4*)(kg + base);
            uint32_t h0 = f2tf(kf.x), h1 = f2tf(kf.y), h2 = f2tf(kf.z), h3 = f2tf(kf.w);
            uint32_t e0 = f2tf(kf.x - __uint_as_float(h0));
            uint32_t e1 = f2tf(kf.y - __uint_as_float(h1));
            uint32_t e2 = f2tf(kf.z - __uint_as_float(h2));
            uint32_t e3 = f2tf(kf.w - __uint_as_float(h3));
            int ck = c4 ^ ((r & 7) << 2);
            uint32_t* kd = (uint32_t*)&Khl[(r * 128 + ck) * 2];
            *(uint4*)kd       = make_uint4(h0, e0, h1, e1);
            *(uint4*)(kd + 4) = make_uint4(h2, e2, h3, e3);

            float4 vf = *(const float4*)(vg + base);
            int cv = c4 ^ ((r & 3) << 3);
            *(uint4*)&Vs[r * 128 + cv] =
                make_uint4(f2tf(vf.x), f2tf(vf.y), f2tf(vf.z), f2tf(vf.w));
        }
        __syncthreads();

        // ---- S = Q K^T  (3xTF32) ----
        float S[6][4];
        #pragma unroll
        for (int nt = 0; nt < 6; ++nt)
            #pragma unroll
            for (int v = 0; v < 4; ++v) S[nt][v] = 0.0f;

        const float* QsW = Qs + woff * 128;
        #pragma unroll
        for (int k8 = 0; k8 < 128; k8 += 8) {
            int ca0 = (k8 + tig)     ^ (gr << 2);
            int ca2 = (k8 + tig + 4) ^ (gr << 2);
            float a0f = QsW[gr * 128 + ca0];
            float a1f = QsW[(gr + 8) * 128 + ca0];
            float a2f = QsW[gr * 128 + ca2];
            float a3f = QsW[(gr + 8) * 128 + ca2];
            uint32_t ah0 = f2tf(a0f), ah1 = f2tf(a1f), ah2 = f2tf(a2f), ah3 = f2tf(a3f);
            uint32_t al0 = f2tf(a0f - __uint_as_float(ah0));
            uint32_t al1 = f2tf(a1f - __uint_as_float(ah1));
            uint32_t al2 = f2tf(a2f - __uint_as_float(ah2));
            uint32_t al3 = f2tf(a3f - __uint_as_float(ah3));
            #pragma unroll
            for (int nt = 0; nt < 6; ++nt) {
                int kvr = (nt << 3) + gr;                 // B n-index (kv row)
                int cb0 = (k8 + tig)     ^ ((kvr & 7) << 2);
                int cb1 = (k8 + tig + 4) ^ ((kvr & 7) << 2);
                uint2 b0 = *(const uint2*)&Khl[(kvr * 128 + cb0) * 2];  // (hi,lo)
                uint2 b1 = *(const uint2*)&Khl[(kvr * 128 + cb1) * 2];
                mma8(S[nt], ah0, ah1, ah2, ah3, b0.x, b1.x);  // hi*hi
                mma8(S[nt], ah0, ah1, ah2, ah3, b0.y, b1.y);  // hi*lo
                mma8(S[nt], al0, al1, al2, al3, b0.x, b1.x);  // lo*hi
            }
        }

        // ---- mask ----
        #pragma unroll
        for (int nt = 0; nt < 6; ++nt) {
            int kvb = kv0 + (nt << 3) + (tig << 1);
            int rk0 = regK[kvb], rk1 = regK[kvb + 1];
            if (rq0 != rk0) S[nt][0] -= 100.0f;
            if (rq0 != rk1) S[nt][1] -= 100.0f;
            if (rq1 != rk0) S[nt][2] -= 100.0f;
            if (rq1 != rk1) S[nt][3] -= 100.0f;
        }

        // ---- online softmax (rows gr / gr+8; 4 lanes per row: xor 1,2) ----
        float rm0 = -1e30f, rm1 = -1e30f;
        #pragma unroll
        for (int nt = 0; nt < 6; ++nt) {
            rm0 = fmaxf(rm0, fmaxf(S[nt][0], S[nt][1]));
            rm1 = fmaxf(rm1, fmaxf(S[nt][2], S[nt][3]));
        }
        rm0 = fmaxf(rm0, __shfl_xor_sync(0xffffffffu, rm0, 1));
        rm0 = fmaxf(rm0, __shfl_xor_sync(0xffffffffu, rm0, 2));
        rm1 = fmaxf(rm1, __shfl_xor_sync(0xffffffffu, rm1, 1));
        rm1 = fmaxf(rm1, __shfl_xor_sync(0xffffffffu, rm1, 2));
        float mn0 = fmaxf(m0, rm0), mn1 = fmaxf(m1, rm1);
        float al0f = __expf(m0 - mn0), al1f = __expf(m1 - mn1);
        m0 = mn0; m1 = mn1;
        float rs0 = 0.0f, rs1 = 0.0f;
        #pragma unroll
        for (int nt = 0; nt < 6; ++nt) {
            S[nt][0] = __expf(S[nt][0] - mn0); rs0 += S[nt][0];
            S[nt][1] = __expf(S[nt][1] - mn0); rs0 += S[nt][1];
            S[nt][2] = __expf(S[nt][2] - mn1); rs1 += S[nt][2];
            S[nt][3] = __expf(S[nt][3] - mn1); rs1 += S[nt][3];
        }
        rs0 += __shfl_xor_sync(0xffffffffu, rs0, 1);
        rs0 += __shfl_xor_sync(0xffffffffu, rs0, 2);
        rs1 += __shfl_xor_sync(0xffffffffu, rs1, 1);
        rs1 += __shfl_xor_sync(0xffffffffu, rs1, 2);
        l0 = l0 * al0f + rs0;
        l1 = l1 * al1f + rs1;
        #pragma unroll
        for (int nt = 0; nt < 16; ++nt) {
            O[nt][0] *= al0f; O[nt][1] *= al0f;
            O[nt][2] *= al1f; O[nt][3] *= al1f;
        }

        __syncthreads();   // all warps done reading Khl (K data) before P overwrite

        // ---- stage P (per-warp private region, pitch 68) ----
        #pragma unroll
        for (int nt = 0; nt < 6; ++nt) {
            int c = (nt << 3) + (tig << 1);
            *(float2*)&Pw[gr * 68 + c]       = make_float2(S[nt][0], S[nt][1]);
            *(float2*)&Pw[(gr + 8) * 68 + c] = make_float2(S[nt][2], S[nt][3]);
        }
        __syncwarp();

        // ---- O += P @ V (1-pass tf32) ----
        #pragma unroll
        for (int k8 = 0; k8 < KVT; k8 += 8) {
            uint32_t pa0 = f2tf(Pw[gr * 68 + k8 + tig]);
            uint32_t pa1 = f2tf(Pw[(gr + 8) * 68 + k8 + tig]);
            uint32_t pa2 = f2tf(Pw[gr * 68 + k8 + tig + 4]);
            uint32_t pa3 = f2tf(Pw[(gr + 8) * 68 + k8 + tig + 4]);
            int kvr = k8 + tig;
            int swv = (kvr & 3) << 3;
            #pragma unroll
            for (int nt = 0; nt < 16; ++nt) {
                int cv = ((nt << 3) + gr) ^ swv;
                uint32_t v0 = __float_as_uint(Vs[kvr * 128 + cv]);
                uint32_t v1 = __float_as_uint(Vs[(kvr + 4) * 128 + cv]);
                mma8(O[nt], pa0, pa1, pa2, pa3, v0, v1);
            }
        }
    }

    // ---- epilogue: normalize + scatter (roll-back == same map) ----
    float inv0 = 1.0f / l0, inv1 = 1.0f / l1;
    int ql0 = q0 + woff + gr;
    int i0 = ql0 / 24, j0 = ql0 - 24 * i0;
    int gr0 = (sh * 24 + i0 + 12) % 96, gc0 = (sw * 24 + j0 + 12) % 96;
    int ql1 = ql0 + 8;
    int i1 = ql1 / 24, j1 = ql1 - 24 * i1;
    int gr1 = (sh * 24 + i1 + 12) % 96, gc1 = (sw * 24 + j1 + 12) % 96;
    float* d0 = outg + ((size_t)(b * 9216 + gr0 * 96 + gc0) << 7);
    float* d1 = outg + ((size_t)(b * 9216 + gr1 * 96 + gc1) << 7);
    #pragma unroll
    for (int nt = 0; nt < 16; ++nt) {
        int c = (nt << 3) + (tig << 1);
        *(float2*)(d0 + c) = make_float2(O[nt][0] * inv0, O[nt][1] * inv0);
        *(float2*)(d1 + c) = make_float2(O[nt][2] * inv1, O[nt][3] * inv1);
    }
}

extern "C" void kernel_launch(void* const* d_in, const int* in_sizes, int n_in,
                              void* d_out, int out_size)
{
    const float* q = (const float*)d_in[0];
    const float* k = (const float*)d_in[1];
    const float* v = (const float*)d_in[2];
    float* out = (float*)d_out;

    cudaFuncSetAttribute(mv_attn_tc,
                         cudaFuncAttributeMaxDynamicSharedMemorySize, SMEM_BYTES);

    dim3 grid(9, 128, 1);
    mv_attn_tc<<<grid, NT, SMEM_BYTES>>>(q, k, v, out);
}

// round 3
// speedup vs baseline: 1.6601x; 1.0221x over previous
#include <cuda_runtime.h>
#include <cstdint>

// Shifted-window multi-view attention, tf32 tensor-core flash kernel, v3.
// B=8, M=3, H=W=96, C=128, NS=4 -> 128 windows, L=576, KV=1728.
// CTA: 256 threads (8 warps), 64 q rows. Warp pair p=(warp>>1) owns q rows
// 16p..16p+15; sub s=(warp&1) computes S for kv half s*16..s*16+15 and PV for
// channel half s*64..s*64+63. KV tile = 32.
// QK^T in 3xTF32 (hi/lo split), PV in 1-pass tf32 (P,V rounded to tf32).

#define NT 256
#define KVT 32

// smem layout (float offsets)
#define QS_OFF   0          // [64][128] fp32 scaled, swz c^((r&7)<<2)      8192
#define KHL_OFF  8192       // [32][128]x2 interleaved hi/lo tf32           8192
#define VS_OFF   16384      // [32][128] tf32, swz c^((r&3)<<3)             4096
#define PB_OFF   20480      // [64][36] tf32 (pitch 36)                     2304
#define MX_OFF   22784      // [2][4][16] row maxes per sub/pair            128
#define SM_OFF   22912      // [2][4][16] row sums                          128
#define SMEM_F   23040
#define REGK_B   (SMEM_F * 4)
#define SMEM_BYTES (REGK_B + 1792)   // + regK[1728] chars  -> 93888 B

__device__ __forceinline__ uint32_t f2tf(float x) {
    uint32_t r; asm("cvt.rna.tf32.f32 %0, %1;" : "=r"(r) : "f"(x)); return r;
}
__device__ __forceinline__ void mma8(float c[4],
    uint32_t a0, uint32_t a1, uint32_t a2, uint32_t a3, uint32_t b0, uint32_t b1) {
    asm volatile("mma.sync.aligned.m16n8k8.row.col.f32.tf32.tf32.f32 "
        "{%0,%1,%2,%3},{%4,%5,%6,%7},{%8,%9},{%0,%1,%2,%3};"
        : "+f"(c[0]), "+f"(c[1]), "+f"(c[2]), "+f"(c[3])
        : "r"(a0), "r"(a1), "r"(a2), "r"(a3), "r"(b0), "r"(b1));
}
__device__ __forceinline__ int reg1(int x) { return (x < 72) ? 0 : ((x < 84) ? 1 : 2); }

extern "C" __global__ void __launch_bounds__(NT, 2)
mv_attn_tc3(const float* __restrict__ qg,
            const float* __restrict__ kg,
            const float* __restrict__ vg,
            float* __restrict__ outg)
{
    extern __shared__ float smem[];
    float* Qs  = smem + QS_OFF;
    float* Khl = smem + KHL_OFF;
    float* Vs  = smem + VS_OFF;
    float* Pb  = smem + PB_OFF;
    float* MX  = smem + MX_OFF;
    float* SMB = smem + SM_OFF;
    char*  regK = (char*)smem + REGK_B;

    const int tid  = threadIdx.x;
    const int warp = tid >> 5;
    const int lane = tid & 31;
    const int gr   = lane >> 2;
    const int tig  = lane & 3;
    const int pair = warp >> 1;     // 0..3
    const int s    = warp & 1;      // 0..1
    const int woff = pair << 4;     // 16 q rows per pair

    const int win = blockIdx.y;
    const int b   = win >> 4;
    const int sh  = (win >> 2) & 3;
    const int sw  = win & 3;
    const int q0  = blockIdx.x << 6;

    const float scale = 0.08838834764831845f;  // 1/sqrt(128)

    // ---- load Q (scaled, swizzled fp32) ----
    #pragma unroll
    for (int it = 0; it < 8; ++it) {
        int idx = tid + it * NT;            // 0..2047
        int r   = idx >> 5;                 // 0..63
        int c4  = (idx & 31) << 2;
        int ql  = q0 + r;
        int i = ql / 24, j = ql - 24 * i;
        int grow = (sh * 24 + i + 12) % 96;
        int gcol = (sw * 24 + j + 12) % 96;
        float4 f = *(const float4*)(qg + ((size_t)(b * 9216 + grow * 96 + gcol) << 7) + c4);
        int cs = c4 ^ ((r & 7) << 2);
        *(float4*)&Qs[r * 128 + cs] =
            make_float4(f.x * scale, f.y * scale, f.z * scale, f.w * scale);
    }
    // ---- region ids for all 1728 kv columns (tile() quirk: col = kv % 576) ----
    for (int idx = tid; idx < 1728; idx += NT) {
        int kcol = idx % 576;
        int i = kcol / 24, j = kcol - 24 * i;
        regK[idx] = (char)(reg1(sh * 24 + i) * 3 + reg1(sw * 24 + j));
    }

    // region ids for my pair's 2 rows
    int rq0, rq1;
    {
        int ql = q0 + woff + gr;
        int i = ql / 24, j = ql - 24 * i;
        rq0 = reg1(sh * 24 + i) * 3 + reg1(sw * 24 + j);
        ql += 8; i = ql / 24; j = ql - 24 * i;
        rq1 = reg1(sh * 24 + i) * 3 + reg1(sw * 24 + j);
    }

    float O[8][4];
    #pragma unroll
    for (int nt = 0; nt < 8; ++nt)
        #pragma unroll
        for (int v = 0; v < 4; ++v) O[nt][v] = 0.0f;
    float m0 = -1e30f, m1 = -1e30f, l0 = 0.0f, l1 = 0.0f;

    const int kvsub = s << 4;        // this warp's kv sub-offset within the tile
    const int cbase = s << 6;        // this warp's channel half for PV

    for (int kv0 = 0; kv0 < 1728; kv0 += KVT) {
        __syncthreads();   // previous iteration's PV readers of Vs/Pb done

        // ---- load K tile -> (hi,lo) tf32 pairs, V tile -> tf32 ----
        #pragma unroll
        for (int it = 0; it < 4; ++it) {
            int idx = tid + it * NT;        // 0..1023
            int r   = idx >> 5;             // 0..31
            int c4  = (idx & 31) << 2;
            int kv  = kv0 + r;
            int l   = kv / 3;
            int mm  = kv - 3 * l;
            int i = l / 24, j = l - 24 * i;
            int grow = (sh * 24 + i + 12) % 96;
            int gcol = (sw * 24 + j + 12) % 96;
            size_t base = (((size_t)(b * 3 + mm) * 9216 + grow * 96 + gcol) << 7) + c4;

            float4 kf = *(const float4*)(kg + base);
            uint32_t h0 = f2tf(kf.x), h1 = f2tf(kf.y), h2 = f2tf(kf.z), h3 = f2tf(kf.w);
            uint32_t e0 = f2tf(kf.x - __uint_as_float(h0));
            uint32_t e1 = f2tf(kf.y - __uint_as_float(h1));
            uint32_t e2 = f2tf(kf.z - __uint_as_float(h2));
            uint32_t e3 = f2tf(kf.w - __uint_as_float(h3));
            int ck = c4 ^ ((r & 7) << 2);
            uint32_t* kd = (uint32_t*)&Khl[(r * 128 + ck) * 2];
            *(uint4*)kd       = make_uint4(h0, e0, h1, e1);
            *(uint4*)(kd + 4) = make_uint4(h2, e2, h3, e3);

            float4 vf = *(const float4*)(vg + base);
            int cv = c4 ^ ((r & 3) << 3);
            *(uint4*)&Vs[r * 128 + cv] =
                make_uint4(f2tf(vf.x), f2tf(vf.y), f2tf(vf.z), f2tf(vf.w));
        }
        __syncthreads();

        // ---- S = Q K^T for this warp's 16 kv rows (3xTF32) ----
        float S[2][4];
        #pragma unroll
        for (int nt = 0; nt < 2; ++nt)
            #pragma unroll
            for (int v = 0; v < 4; ++v) S[nt][v] = 0.0f;

        const float* QsW = Qs + woff * 128;
        #pragma unroll
        for (int k8 = 0; k8 < 128; k8 += 8) {
            int ca0 = (k8 + tig)     ^ (gr << 2);
            int ca2 = (k8 + tig + 4) ^ (gr << 2);
            float a0f = QsW[gr * 128 + ca0];
            float a1f = QsW[(gr + 8) * 128 + ca0];
            float a2f = QsW[gr * 128 + ca2];
            float a3f = QsW[(gr + 8) * 128 + ca2];
            uint32_t ah0 = f2tf(a0f), ah1 = f2tf(a1f), ah2 = f2tf(a2f), ah3 = f2tf(a3f);
            uint32_t al0 = f2tf(a0f - __uint_as_float(ah0));
            uint32_t al1 = f2tf(a1f - __uint_as_float(ah1));
            uint32_t al2 = f2tf(a2f - __uint_as_float(ah2));
            uint32_t al3 = f2tf(a3f - __uint_as_float(ah3));
            #pragma unroll
            for (int nt = 0; nt < 2; ++nt) {
                int kvr = kvsub + (nt << 3) + gr;          // smem kv row
                int cb0 = (k8 + tig)     ^ ((kvr & 7) << 2);
                int cb1 = (k8 + tig + 4) ^ ((kvr & 7) << 2);
                uint2 b0 = *(const uint2*)&Khl[(kvr * 128 + cb0) * 2];
                uint2 b1 = *(const uint2*)&Khl[(kvr * 128 + cb1) * 2];
                mma8(S[nt], ah0, ah1, ah2, ah3, b0.x, b1.x);  // hi*hi
                mma8(S[nt], ah0, ah1, ah2, ah3, b0.y, b1.y);  // hi*lo
                mma8(S[nt], al0, al1, al2, al3, b0.x, b1.x);  // lo*hi
            }
        }

        // ---- mask ----
        #pragma unroll
        for (int nt = 0; nt < 2; ++nt) {
            int kvb = kv0 + kvsub + (nt << 3) + (tig << 1);
            int rk0 = regK[kvb], rk1 = regK[kvb + 1];
            if (rq0 != rk0) S[nt][0] -= 100.0f;
            if (rq0 != rk1) S[nt][1] -= 100.0f;
            if (rq1 != rk0) S[nt][2] -= 100.0f;
            if (rq1 != rk1) S[nt][3] -= 100.0f;
        }

        // ---- partial row max (this warp's 16 kv) ----
        float rm0 = fmaxf(fmaxf(S[0][0], S[0][1]), fmaxf(S[1][0], S[1][1]));
        float rm1 = fmaxf(fmaxf(S[0][2], S[0][3]), fmaxf(S[1][2], S[1][3]));
        rm0 = fmaxf(rm0, __shfl_xor_sync(0xffffffffu, rm0, 1));
        rm0 = fmaxf(rm0, __shfl_xor_sync(0xffffffffu, rm0, 2));
        rm1 = fmaxf(rm1, __shfl_xor_sync(0xffffffffu, rm1, 1));
        rm1 = fmaxf(rm1, __shfl_xor_sync(0xffffffffu, rm1, 2));
        if (tig == 0) {
            MX[(s << 6) + (pair << 4) + gr]     = rm0;
            MX[(s << 6) + (pair << 4) + gr + 8] = rm1;
        }
        __syncthreads();

        // ---- combine pair maxes, exp, stage P (tf32), partial sums ----
        float fm0 = fmaxf(MX[(pair << 4) + gr],     MX[64 + (pair << 4) + gr]);
        float fm1 = fmaxf(MX[(pair << 4) + gr + 8], MX[64 + (pair << 4) + gr + 8]);
        float mn0 = fmaxf(m0, fm0), mn1 = fmaxf(m1, fm1);
        float al0f = __expf(m0 - mn0), al1f = __expf(m1 - mn1);
        m0 = mn0; m1 = mn1;

        float rs0 = 0.0f, rs1 = 0.0f;
        #pragma unroll
        for (int nt = 0; nt < 2; ++nt) {
            float p0 = __expf(S[nt][0] - mn0);
            float p1 = __expf(S[nt][1] - mn0);
            float p2 = __expf(S[nt][2] - mn1);
            float p3 = __expf(S[nt][3] - mn1);
            rs0 += p0 + p1; rs1 += p2 + p3;
            int c = kvsub + (nt << 3) + (tig << 1);
            uint32_t* prow0 = (uint32_t*)&Pb[(woff + gr) * 36 + c];
            uint32_t* prow1 = (uint32_t*)&Pb[(woff + gr + 8) * 36 + c];
            prow0[0] = f2tf(p0); prow0[1] = f2tf(p1);
            prow1[0] = f2tf(p2); prow1[1] = f2tf(p3);
        }
        rs0 += __shfl_xor_sync(0xffffffffu, rs0, 1);
        rs0 += __shfl_xor_sync(0xffffffffu, rs0, 2);
        rs1 += __shfl_xor_sync(0xffffffffu, rs1, 1);
        rs1 += __shfl_xor_sync(0xffffffffu, rs1, 2);
        if (tig == 0) {
            SMB[(s << 6) + (pair << 4) + gr]     = rs0;
            SMB[(s << 6) + (pair << 4) + gr + 8] = rs1;
        }
        __syncthreads();

        float sum0 = SMB[(pair << 4) + gr]     + SMB[64 + (pair << 4) + gr];
        float sum1 = SMB[(pair << 4) + gr + 8] + SMB[64 + (pair << 4) + gr + 8];
        l0 = l0 * al0f + sum0;
        l1 = l1 * al1f + sum1;
        #pragma unroll
        for (int nt = 0; nt < 8; ++nt) {
            O[nt][0] *= al0f; O[nt][1] *= al0f;
            O[nt][2] *= al1f; O[nt][3] *= al1f;
        }

        // ---- O += P @ V on this warp's 64 channels ----
        const float* Pw = Pb + woff * 36;
        #pragma unroll
        for (int k8 = 0; k8 < KVT; k8 += 8) {
            uint32_t pa0 = __float_as_uint(Pw[gr * 36 + k8 + tig]);
            uint32_t pa1 = __float_as_uint(Pw[(gr + 8) * 36 + k8 + tig]);
            uint32_t pa2 = __float_as_uint(Pw[gr * 36 + k8 + tig + 4]);
            uint32_t pa3 = __float_as_uint(Pw[(gr + 8) * 36 + k8 + tig + 4]);
            int kvr = k8 + tig;
            int swv = (kvr & 3) << 3;
            #pragma unroll
            for (int nt = 0; nt < 8; ++nt) {
                int cv = (cbase + (nt << 3) + gr) ^ swv;
                uint32_t v0 = __float_as_uint(Vs[kvr * 128 + cv]);
                uint32_t v1 = __float_as_uint(Vs[(kvr + 4) * 128 + cv]);
                mma8(O[nt], pa0, pa1, pa2, pa3, v0, v1);
            }
        }
    }

    // ---- epilogue: normalize + scatter ----
    float inv0 = 1.0f / l0, inv1 = 1.0f / l1;
    int ql0 = q0 + woff + gr;
    int i0 = ql0 / 24, j0 = ql0 - 24 * i0;
    int gr0 = (sh * 24 + i0 + 12) % 96, gc0 = (sw * 24 + j0 + 12) % 96;
    int ql1 = ql0 + 8;
    int i1 = ql1 / 24, j1 = ql1 - 24 * i1;
    int gr1 = (sh * 24 + i1 + 12) % 96, gc1 = (sw * 24 + j1 + 12) % 96;
    float* d0 = outg + ((size_t)(b * 9216 + gr0 * 96 + gc0) << 7) + cbase;
    float* d1 = outg + ((size_t)(b * 9216 + gr1 * 96 + gc1) << 7) + cbase;
    #pragma unroll
    for (int nt = 0; nt < 8; ++nt) {
        int c = (nt << 3) + (tig << 1);
        *(float2*)(d0 + c) = make_float2(O[nt][0] * inv0, O[nt][1] * inv0);
        *(float2*)(d1 + c) = make_float2(O[nt][2] * inv1, O[nt][3] * inv1);
    }
}

extern "C" void kernel_launch(void* const* d_in, const int* in_sizes, int n_in,
                              void* d_out, int out_size)
{
    const float* q = (const float*)d_in[0];
    const float* k = (const float*)d_in[1];
    const float* v = (const float*)d_in[2];
    float* out = (float*)d_out;

    cudaFuncSetAttribute(mv_attn_tc3,
                         cudaFuncAttributeMaxDynamicSharedMemorySize, SMEM_BYTES);

    dim3 grid(9, 128, 1);
    mv_attn_tc3<<<grid, NT, SMEM_BYTES>>>(q, k, v, out);
}

// round 4
// speedup vs baseline: 2.9290x; 1.7643x over previous
#include <cuda_runtime.h>
#include <cuda_bf16.h>
#include <cstdint>

// Shifted-window multi-view attention, v4.
// B=8, M=3, H=W=96, C=128, NS=4 -> 128 windows, L=576, KV=1728.
// Two kernels:
//  1) prep_kv: gather K/V into per-window scratch; K split to bf16 hi/lo
//     planes (bf16x2 channel pairs), V rounded to tf32.
//  2) mv_attn_tc4: flash attention. QK^T = 3xBF16 (m16n8k16):
//     Qhi*Khi + Qhi*Klo + Qlo*Khi  (error ~2^-18, fp32-grade for scores).
//     PV = 1-pass tf32 (m16n8k8). Q pre-split to bf16 hi/lo in smem.
// CTA: 256 thr (8 warps), 64 q rows; warp pair owns 16 rows; sub s=warp&1
// handles kv half (24 -> nt=3) for S and channel half (64) for PV. KVT=48.

#define NT 256
#define KVT 48
#define NWIN 128
#define KVLEN 1728

// ---- scratch (static device arrays; no runtime allocation) ----
__device__ uint32_t g_Khi[(size_t)NWIN * KVLEN * 64];   // bf16x2 per 2 ch
__device__ uint32_t g_Klo[(size_t)NWIN * KVLEN * 64];
__device__ float    g_Vt [(size_t)NWIN * KVLEN * 128];  // tf32

// ---- smem word offsets ----
#define QHI_OFF 0        // [64][64] u32 (bf16x2 pairs), swz p^((r&7)<<2)
#define QLO_OFF 4096
#define KHI_OFF 8192     // [48][64] u32, swz p^((r&7)<<2)  (P overlays here)
#define KLO_OFF 11264
#define VS_OFF  14336    // [48][128] f32 tf32, swz c^((r&3)<<3)
#define MX_OFF  20480    // [2][4][16]
#define SM_OFF  20608
#define SMEM_F  20736
#define REGK_B  (SMEM_F * 4)
#define SMEM_BYTES (REGK_B + KVLEN)   // 84672 B
#define P_PITCH 52

__device__ __forceinline__ uint32_t f2tf(float x) {
    uint32_t r; asm("cvt.rna.tf32.f32 %0, %1;" : "=r"(r) : "f"(x)); return r;
}
__device__ __forceinline__ uint32_t bfbits(__nv_bfloat162 h) {
    return *reinterpret_cast<uint32_t*>(&h);
}
__device__ __forceinline__ void mma16(float c[4],
    uint32_t a0, uint32_t a1, uint32_t a2, uint32_t a3, uint32_t b0, uint32_t b1) {
    asm volatile("mma.sync.aligned.m16n8k16.row.col.f32.bf16.bf16.f32 "
        "{%0,%1,%2,%3},{%4,%5,%6,%7},{%8,%9},{%0,%1,%2,%3};"
        : "+f"(c[0]), "+f"(c[1]), "+f"(c[2]), "+f"(c[3])
        : "r"(a0), "r"(a1), "r"(a2), "r"(a3), "r"(b0), "r"(b1));
}
__device__ __forceinline__ void mma8(float c[4],
    uint32_t a0, uint32_t a1, uint32_t a2, uint32_t a3, uint32_t b0, uint32_t b1) {
    asm volatile("mma.sync.aligned.m16n8k8.row.col.f32.tf32.tf32.f32 "
        "{%0,%1,%2,%3},{%4,%5,%6,%7},{%8,%9},{%0,%1,%2,%3};"
        : "+f"(c[0]), "+f"(c[1]), "+f"(c[2]), "+f"(c[3])
        : "r"(a0), "r"(a1), "r"(a2), "r"(a3), "r"(b0), "r"(b1));
}
__device__ __forceinline__ int reg1(int x) { return (x < 72) ? 0 : ((x < 84) ? 1 : 2); }

// ============ prep: gather + convert K/V into window-major scratch ============
extern "C" __global__ void __launch_bounds__(256)
prep_kv(const float* __restrict__ kg, const float* __restrict__ vg)
{
    int g = blockIdx.x * 256 + threadIdx.x;     // 0 .. 128*1728*32-1
    int win = g / 55296;                        // 1728*32
    int rem = g - win * 55296;
    int kv  = rem >> 5;
    int c4  = (rem & 31) << 2;
    int b = win >> 4, sh = (win >> 2) & 3, sw = win & 3;
    int l = kv / 3, mm = kv - 3 * l;
    int i = l / 24, j = l - 24 * i;
    int grow = (sh * 24 + i + 12) % 96;
    int gcol = (sw * 24 + j + 12) % 96;
    size_t src = (((size_t)((b * 3 + mm) * 9216 + grow * 96 + gcol)) << 7) + c4;

    float4 kf = *(const float4*)(kg + src);
    __nv_bfloat162 h0 = __floats2bfloat162_rn(kf.x, kf.y);
    __nv_bfloat162 h1 = __floats2bfloat162_rn(kf.z, kf.w);
    __nv_bfloat162 l0 = __floats2bfloat162_rn(kf.x - __low2float(h0),
                                              kf.y - __high2float(h0));
    __nv_bfloat162 l1 = __floats2bfloat162_rn(kf.z - __low2float(h1),
                                              kf.w - __high2float(h1));
    size_t dst = (size_t)win * (KVLEN * 64) + (size_t)kv * 64 + (c4 >> 1);
    *(uint2*)(g_Khi + dst) = make_uint2(bfbits(h0), bfbits(h1));
    *(uint2*)(g_Klo + dst) = make_uint2(bfbits(l0), bfbits(l1));

    float4 vf = *(const float4*)(vg + src);
    size_t dv = (size_t)win * (KVLEN * 128) + (size_t)kv * 128 + c4;
    *(uint4*)(g_Vt + dv) = make_uint4(f2tf(vf.x), f2tf(vf.y), f2tf(vf.z), f2tf(vf.w));
}

// ============ main attention kernel ============
extern "C" __global__ void __launch_bounds__(NT, 2)
mv_attn_tc4(const float* __restrict__ qg, float* __restrict__ outg)
{
    extern __shared__ float smem[];
    uint32_t* QhiS = (uint32_t*)smem + QHI_OFF;
    uint32_t* QloS = (uint32_t*)smem + QLO_OFF;
    uint32_t* KhiS = (uint32_t*)smem + KHI_OFF;
    uint32_t* KloS = (uint32_t*)smem + KLO_OFF;
    float*    Vs   = smem + VS_OFF;
    float*    MX   = smem + MX_OFF;
    float*    SMB  = smem + SM_OFF;
    float*    Pb   = smem + KHI_OFF;       // P overlay on K planes
    char*     regK = (char*)smem + REGK_B;

    const int tid  = threadIdx.x;
    const int warp = tid >> 5;
    const int lane = tid & 31;
    const int gr   = lane >> 2;
    const int tig  = lane & 3;
    const int pair = warp >> 1;
    const int s    = warp & 1;
    const int woff = pair << 4;

    const int win = blockIdx.y;
    const int b   = win >> 4;
    const int sh  = (win >> 2) & 3;
    const int sw  = win & 3;
    const int q0  = blockIdx.x << 6;

    const float scale = 0.08838834764831845f;   // 1/sqrt(128)
    const size_t wb64  = (size_t)win * (KVLEN * 64);
    const size_t wb128 = (size_t)win * (KVLEN * 128);

    // ---- load Q (gather + scale + bf16 hi/lo split into smem) ----
    #pragma unroll
    for (int it = 0; it < 8; ++it) {
        int idx = tid + it * NT;           // 0..2047
        int r   = idx >> 5;                // 0..63
        int c4  = (idx & 31) << 2;
        int ql  = q0 + r;
        int i = ql / 24, j = ql - 24 * i;
        int grow = (sh * 24 + i + 12) % 96;
        int gcol = (sw * 24 + j + 12) % 96;
        float4 f = *(const float4*)(qg + ((size_t)(b * 9216 + grow * 96 + gcol) << 7) + c4);
        f.x *= scale; f.y *= scale; f.z *= scale; f.w *= scale;
        __nv_bfloat162 h0 = __floats2bfloat162_rn(f.x, f.y);
        __nv_bfloat162 h1 = __floats2bfloat162_rn(f.z, f.w);
        __nv_bfloat162 l0 = __floats2bfloat162_rn(f.x - __low2float(h0),
                                                  f.y - __high2float(h0));
        __nv_bfloat162 l1 = __floats2bfloat162_rn(f.z - __low2float(h1),
                                                  f.w - __high2float(h1));
        int ps = (c4 >> 1) ^ ((r & 7) << 2);
        *(uint2*)&QhiS[r * 64 + ps] = make_uint2(bfbits(h0), bfbits(h1));
        *(uint2*)&QloS[r * 64 + ps] = make_uint2(bfbits(l0), bfbits(l1));
    }
    // ---- region LUT for all kv columns (tile() quirk: col = kv % 576) ----
    for (int idx = tid; idx < KVLEN; idx += NT) {
        int kcol = idx % 576;
        int i = kcol / 24, j = kcol - 24 * i;
        regK[idx] = (char)(reg1(sh * 24 + i) * 3 + reg1(sw * 24 + j));
    }

    int rq0, rq1;
    {
        int ql = q0 + woff + gr;
        int i = ql / 24, j = ql - 24 * i;
        rq0 = reg1(sh * 24 + i) * 3 + reg1(sw * 24 + j);
        ql += 8; i = ql / 24; j = ql - 24 * i;
        rq1 = reg1(sh * 24 + i) * 3 + reg1(sw * 24 + j);
    }

    float O[8][4];
    #pragma unroll
    for (int nt = 0; nt < 8; ++nt)
        #pragma unroll
        for (int v = 0; v < 4; ++v) O[nt][v] = 0.0f;
    float m0 = -1e30f, m1 = -1e30f, l0s = 0.0f, l1s = 0.0f;

    const int kvsub = s * 24;      // kv half for S (nt=3 -> 24 rows)
    const int cbase = s << 6;      // channel half for PV

    for (int kv0 = 0; kv0 < KVLEN; kv0 += KVT) {
        __syncthreads();   // prior PV readers of Vs/Pb done

        // ---- K planes: 48 rows x 16 uint4 per plane ----
        #pragma unroll
        for (int it = 0; it < 3; ++it) {
            int idx = tid + it * NT;           // 0..767
            int r   = idx >> 4;                // 0..47
            int p4  = (idx & 15) << 2;
            int pk  = p4 ^ ((r & 7) << 2);
            size_t srcp = wb64 + (size_t)(kv0 + r) * 64 + p4;
            *(uint4*)&KhiS[r * 64 + pk] = *(const uint4*)(g_Khi + srcp);
            *(uint4*)&KloS[r * 64 + pk] = *(const uint4*)(g_Klo + srcp);
        }
        // ---- V: 48 rows x 32 float4 ----
        #pragma unroll
        for (int it = 0; it < 6; ++it) {
            int idx = tid + it * NT;           // 0..1535
            int r   = idx >> 5;                // 0..47
            int c4  = (idx & 31) << 2;
            int cv  = c4 ^ ((r & 3) << 3);
            *(float4*)&Vs[r * 128 + cv] =
                *(const float4*)(g_Vt + wb128 + (size_t)(kv0 + r) * 128 + c4);
        }
        __syncthreads();

        // ---- S = Q K^T (3xBF16, m16n8k16) ----
        float S[3][4];
        #pragma unroll
        for (int nt = 0; nt < 3; ++nt)
            #pragma unroll
            for (int v = 0; v < 4; ++v) S[nt][v] = 0.0f;

        const int sA = gr << 2;
        #pragma unroll
        for (int step = 0; step < 8; ++step) {
            int pp = (step << 3) + tig;
            int pA0 = pp ^ sA, pA1 = (pp + 4) ^ sA;
            uint32_t ah0 = QhiS[(woff + gr) * 64 + pA0];
            uint32_t ah1 = QhiS[(woff + gr + 8) * 64 + pA0];
            uint32_t ah2 = QhiS[(woff + gr) * 64 + pA1];
            uint32_t ah3 = QhiS[(woff + gr + 8) * 64 + pA1];
            uint32_t al0 = QloS[(woff + gr) * 64 + pA0];
            uint32_t al1 = QloS[(woff + gr + 8) * 64 + pA0];
            uint32_t al2 = QloS[(woff + gr) * 64 + pA1];
            uint32_t al3 = QloS[(woff + gr + 8) * 64 + pA1];

            uint32_t bh[3][2], bl[3][2];
            #pragma unroll
            for (int nt = 0; nt < 3; ++nt) {
                int kvr = kvsub + (nt << 3) + gr;
                int rb  = kvr * 64;
                int sB  = (kvr & 7) << 2;
                bh[nt][0] = KhiS[rb + (pp ^ sB)];
                bh[nt][1] = KhiS[rb + ((pp + 4) ^ sB)];
                bl[nt][0] = KloS[rb + (pp ^ sB)];
                bl[nt][1] = KloS[rb + ((pp + 4) ^ sB)];
            }
            #pragma unroll
            for (int nt = 0; nt < 3; ++nt)
                mma16(S[nt], ah0, ah1, ah2, ah3, bh[nt][0], bh[nt][1]);
            #pragma unroll
            for (int nt = 0; nt < 3; ++nt)
                mma16(S[nt], ah0, ah1, ah2, ah3, bl[nt][0], bl[nt][1]);
            #pragma unroll
            for (int nt = 0; nt < 3; ++nt)
                mma16(S[nt], al0, al1, al2, al3, bh[nt][0], bh[nt][1]);
        }

        // ---- mask ----
        #pragma unroll
        for (int nt = 0; nt < 3; ++nt) {
            int kvb = kv0 + kvsub + (nt << 3) + (tig << 1);
            int rk0 = regK[kvb], rk1 = regK[kvb + 1];
            if (rq0 != rk0) S[nt][0] -= 100.0f;
            if (rq0 != rk1) S[nt][1] -= 100.0f;
            if (rq1 != rk0) S[nt][2] -= 100.0f;
            if (rq1 != rk1) S[nt][3] -= 100.0f;
        }

        // ---- partial row max ----
        float rm0 = -1e30f, rm1 = -1e30f;
        #pragma unroll
        for (int nt = 0; nt < 3; ++nt) {
            rm0 = fmaxf(rm0, fmaxf(S[nt][0], S[nt][1]));
            rm1 = fmaxf(rm1, fmaxf(S[nt][2], S[nt][3]));
        }
        rm0 = fmaxf(rm0, __shfl_xor_sync(0xffffffffu, rm0, 1));
        rm0 = fmaxf(rm0, __shfl_xor_sync(0xffffffffu, rm0, 2));
        rm1 = fmaxf(rm1, __shfl_xor_sync(0xffffffffu, rm1, 1));
        rm1 = fmaxf(rm1, __shfl_xor_sync(0xffffffffu, rm1, 2));
        if (tig == 0) {
            MX[(s << 6) + (pair << 4) + gr]     = rm0;
            MX[(s << 6) + (pair << 4) + gr + 8] = rm1;
        }
        __syncthreads();   // also: all QK reads of K planes done -> P overlay safe

        float fm0 = fmaxf(MX[(pair << 4) + gr],     MX[64 + (pair << 4) + gr]);
        float fm1 = fmaxf(MX[(pair << 4) + gr + 8], MX[64 + (pair << 4) + gr + 8]);
        float mn0 = fmaxf(m0, fm0), mn1 = fmaxf(m1, fm1);
        float a0f = __expf(m0 - mn0), a1f = __expf(m1 - mn1);
        m0 = mn0; m1 = mn1;

        float rs0 = 0.0f, rs1 = 0.0f;
        #pragma unroll
        for (int nt = 0; nt < 3; ++nt) {
            float p0 = __expf(S[nt][0] - mn0);
            float p1 = __expf(S[nt][1] - mn0);
            float p2 = __expf(S[nt][2] - mn1);
            float p3 = __expf(S[nt][3] - mn1);
            rs0 += p0 + p1; rs1 += p2 + p3;
            int c = kvsub + (nt << 3) + (tig << 1);
            uint32_t* pr0 = (uint32_t*)&Pb[(woff + gr) * P_PITCH + c];
            uint32_t* pr1 = (uint32_t*)&Pb[(woff + gr + 8) * P_PITCH + c];
            pr0[0] = f2tf(p0); pr0[1] = f2tf(p1);
            pr1[0] = f2tf(p2); pr1[1] = f2tf(p3);
        }
        rs0 += __shfl_xor_sync(0xffffffffu, rs0, 1);
        rs0 += __shfl_xor_sync(0xffffffffu, rs0, 2);
        rs1 += __shfl_xor_sync(0xffffffffu, rs1, 1);
        rs1 += __shfl_xor_sync(0xffffffffu, rs1, 2);
        if (tig == 0) {
            SMB[(s << 6) + (pair << 4) + gr]     = rs0;
            SMB[(s << 6) + (pair << 4) + gr + 8] = rs1;
        }
        __syncthreads();

        float sum0 = SMB[(pair << 4) + gr]     + SMB[64 + (pair << 4) + gr];
        float sum1 = SMB[(pair << 4) + gr + 8] + SMB[64 + (pair << 4) + gr + 8];
        l0s = l0s * a0f + sum0;
        l1s = l1s * a1f + sum1;
        #pragma unroll
        for (int nt = 0; nt < 8; ++nt) {
            O[nt][0] *= a0f; O[nt][1] *= a0f;
            O[nt][2] *= a1f; O[nt][3] *= a1f;
        }

        // ---- O += P @ V (tf32) on this warp's 64 channels ----
        const float* Pw = Pb + woff * P_PITCH;
        #pragma unroll
        for (int k8 = 0; k8 < KVT; k8 += 8) {
            uint32_t pa0 = __float_as_uint(Pw[gr * P_PITCH + k8 + tig]);
            uint32_t pa1 = __float_as_uint(Pw[(gr + 8) * P_PITCH + k8 + tig]);
            uint32_t pa2 = __float_as_uint(Pw[gr * P_PITCH + k8 + tig + 4]);
            uint32_t pa3 = __float_as_uint(Pw[(gr + 8) * P_PITCH + k8 + tig + 4]);
            int kvr = k8 + tig;
            int swv = (kvr & 3) << 3;
            #pragma unroll
            for (int nt = 0; nt < 8; ++nt) {
                int cv = (cbase + (nt << 3) + gr) ^ swv;
                uint32_t v0 = __float_as_uint(Vs[kvr * 128 + cv]);
                uint32_t v1 = __float_as_uint(Vs[(kvr + 4) * 128 + cv]);
                mma8(O[nt], pa0, pa1, pa2, pa3, v0, v1);
            }
        }
    }

    // ---- epilogue ----
    float inv0 = 1.0f / l0s, inv1 = 1.0f / l1s;
    int ql0 = q0 + woff + gr;
    int i0 = ql0 / 24, j0 = ql0 - 24 * i0;
    int gr0 = (sh * 24 + i0 + 12) % 96, gc0 = (sw * 24 + j0 + 12) % 96;
    int ql1 = ql0 + 8;
    int i1 = ql1 / 24, j1 = ql1 - 24 * i1;
    int gr1 = (sh * 24 + i1 + 12) % 96, gc1 = (sw * 24 + j1 + 12) % 96;
    float* d0 = outg + ((size_t)(b * 9216 + gr0 * 96 + gc0) << 7) + cbase;
    float* d1 = outg + ((size_t)(b * 9216 + gr1 * 96 + gc1) << 7) + cbase;
    #pragma unroll
    for (int nt = 0; nt < 8; ++nt) {
        int c = (nt << 3) + (tig << 1);
        *(float2*)(d0 + c) = make_float2(O[nt][0] * inv0, O[nt][1] * inv0);
        *(float2*)(d1 + c) = make_float2(O[nt][2] * inv1, O[nt][3] * inv1);
    }
}

extern "C" void kernel_launch(void* const* d_in, const int* in_sizes, int n_in,
                              void* d_out, int out_size)
{
    const float* q = (const float*)d_in[0];
    const float* k = (const float*)d_in[1];
    const float* v = (const float*)d_in[2];
    float* out = (float*)d_out;

    prep_kv<<<27648, 256>>>(k, v);   // 128*1728*32 / 256

    cudaFuncSetAttribute(mv_attn_tc4,
                         cudaFuncAttributeMaxDynamicSharedMemorySize, SMEM_BYTES);
    dim3 grid(9, 128, 1);
    mv_attn_tc4<<<grid, NT, SMEM_BYTES>>>(q, out);
}